// round 16
// baseline (speedup 1.0000x reference)
#include <cuda_runtime.h>
#include <cuda_fp16.h>
#include <cstdint>

#define BB 8
#define LL 1024
#define DD 1024
#define HH 16
#define DKK 64
#define DI 4096
#define MTOK (BB*LL)
#define NREL 33

using fp16 = __half;

// ---------------- scratch (device globals) -----------------------------------
__device__ float g_qrel[(size_t)MTOK*HH*NREL];
__device__ float g_fc[MTOK*DD];
__device__ float g_x1[MTOK*DD];
__device__ float g_y[MTOK*DD];

__device__ fp16 g_wqt[DD*DD];
__device__ fp16 g_wkt[DD*DD];
__device__ fp16 g_wvt[DD*DD];
__device__ fp16 g_wft[DD*DD];
__device__ fp16 g_w1t[(size_t)DI*DD];
__device__ fp16 g_w2t[(size_t)DD*DI];
__device__ fp16 g_qs[MTOK*DD];
__device__ fp16 g_ks[MTOK*DD];
__device__ fp16 g_vs[MTOK*DD];
__device__ fp16 g_Qs[MTOK*DD];
__device__ fp16 g_Kb[MTOK*DD];
__device__ fp16 g_Vp[MTOK*DD];
__device__ fp16 g_Vt[BB*HH*DKK*LL];
__device__ fp16 g_AT[MTOK*DD];
__device__ fp16 g_x1s[MTOK*DD];
__device__ fp16 g_hid[(size_t)MTOK*DI];

// ---------------- helpers -----------------------------------------------------
__device__ __forceinline__ uint32_t smem_u32(const void* p) {
    uint32_t a;
    asm("{ .reg .u64 t; cvta.to.shared.u64 t, %1; cvt.u32.u64 %0, t; }" : "=r"(a) : "l"(p));
    return a;
}
__device__ __forceinline__ uint32_t hpk2(fp16 a, fp16 b) {
    __half2 t = __halves2half2(a, b);
    return *reinterpret_cast<uint32_t*>(&t);
}
__device__ __forceinline__ void ldsm4(uint32_t* r, uint32_t addr) {
    asm volatile("ldmatrix.sync.aligned.m8n8.x4.shared.b16 {%0,%1,%2,%3}, [%4];"
                 : "=r"(r[0]), "=r"(r[1]), "=r"(r[2]), "=r"(r[3]) : "r"(addr));
}
__device__ __forceinline__ void mmaf16(float* d, const uint32_t* a, const uint32_t* b) {
    asm volatile("mma.sync.aligned.m16n8k16.row.col.f32.f16.f16.f32 "
                 "{%0,%1,%2,%3}, {%4,%5,%6,%7}, {%8,%9}, {%0,%1,%2,%3};"
                 : "+f"(d[0]), "+f"(d[1]), "+f"(d[2]), "+f"(d[3])
                 : "r"(a[0]), "r"(a[1]), "r"(a[2]), "r"(a[3]), "r"(b[0]), "r"(b[1]));
}
__device__ __forceinline__ void cpa16(uint32_t s, const void* g) {
    asm volatile("cp.async.cg.shared.global [%0], [%1], 16;" :: "r"(s), "l"(g));
}
#define CP_COMMIT() asm volatile("cp.async.commit_group;" ::: "memory")
#define CP_WAIT1()  asm volatile("cp.async.wait_group 1;" ::: "memory")
#define CP_WAIT0()  asm volatile("cp.async.wait_group 0;" ::: "memory")

// ======== fp16 GEMM: block 128x128, 4 warps (warp 64x64), BK=64, 3-stage ======
// 2 CTA/SM, ONE barrier per K-tile.
// EPI: 0 = +bias, 1 = +bias,relu   STORE: 0 = fp32 C, 1 = fp16 Co
template<int EPI, int STORE>
__global__ void __launch_bounds__(128, 2) hgemm(
    const fp16* __restrict__ A, const fp16* __restrict__ B,
    const float* __restrict__ bias, float* __restrict__ C,
    fp16* __restrict__ Co,
    int K, int lda, int ldb, int ldc)
{
    constexpr int SS = 36864;   // stage: A 128x144B | B 128x144B
    extern __shared__ __align__(16) char dsm[];
    uint32_t ub = smem_u32(dsm);

    int tid = threadIdx.x, wid = tid >> 5, lane = tid & 31;
    int brow = blockIdx.y * 128;
    int bcol = blockIdx.x * 128;
    int wm = (wid & 1) * 64;
    int wn = (wid >> 1) * 64;

    float acc[4][8][4];
#pragma unroll
    for (int mt = 0; mt < 4; mt++)
#pragma unroll
        for (int nt = 0; nt < 8; nt++)
#pragma unroll
            for (int i = 0; i < 4; i++) acc[mt][nt][i] = 0.f;

    const int KT = K >> 6;

#define ISSUE(stg, k0) do {                                                       \
    uint32_t us_ = ub + (stg) * SS;                                               \
    _Pragma("unroll")                                                             \
    for (int i_ = 0; i_ < 8; i_++) {                                              \
        int id_ = i_ * 128 + tid; int r_ = id_ >> 3, c_ = id_ & 7;                \
        cpa16(us_ + r_ * 144 + c_ * 16,                                           \
              A + (size_t)(brow + r_) * lda + (k0) + c_ * 8);                     \
    }                                                                             \
    _Pragma("unroll")                                                             \
    for (int i_ = 0; i_ < 8; i_++) {                                              \
        int id_ = i_ * 128 + tid; int r_ = id_ >> 3, c_ = id_ & 7;                \
        cpa16(us_ + 18432 + r_ * 144 + c_ * 16,                                   \
              B + (size_t)(bcol + r_) * ldb + (k0) + c_ * 8);                     \
    }                                                                             \
} while (0)

    int fetch = 0;
    const int PRE = (2 < KT) ? 2 : KT;
    for (; fetch < PRE; fetch++) { ISSUE(fetch, fetch << 6); CP_COMMIT(); }

    for (int kt = 0; kt < KT; kt++) {
        if (kt == KT - 1) CP_WAIT0(); else CP_WAIT1();
        __syncthreads();                       // also protects stage (kt+2)%3 reuse
        if (fetch < KT) { ISSUE(fetch % 3, fetch << 6); CP_COMMIT(); fetch++; }

        uint32_t us = ub + (kt % 3) * SS;
#pragma unroll
        for (int ks = 0; ks < 4; ks++) {
            uint32_t aH[4][4], bH[8][2];
#pragma unroll
            for (int mt = 0; mt < 4; mt++) {
                uint32_t ar = wm + mt * 16 + (lane & 15);
                uint32_t ac = ks * 16 + ((lane >> 4) << 3);
                ldsm4(aH[mt], us + ar * 144 + ac * 2);
            }
#pragma unroll
            for (int p = 0; p < 4; p++) {
                uint32_t br = wn + p * 16 + ((lane >> 4) << 3) + (lane & 7);
                uint32_t bc = ks * 16 + (((lane >> 3) & 1) << 3);
                uint32_t r[4];
                ldsm4(r, us + 18432 + br * 144 + bc * 2);
                bH[p * 2][0] = r[0]; bH[p * 2][1] = r[1];
                bH[p * 2 + 1][0] = r[2]; bH[p * 2 + 1][1] = r[3];
            }
#pragma unroll
            for (int mt = 0; mt < 4; mt++)
#pragma unroll
                for (int nt = 0; nt < 8; nt++)
                    mmaf16(acc[mt][nt], aH[mt], bH[nt]);
        }
        // no trailing barrier: next iteration's top barrier covers the hazard
    }
#undef ISSUE

    // epilogue
#pragma unroll
    for (int mt = 0; mt < 4; mt++) {
#pragma unroll
        for (int nt = 0; nt < 8; nt++) {
            int r0 = brow + wm + mt * 16 + (lane >> 2);
            int c0 = bcol + wn + nt * 8 + ((lane & 3) << 1);
#pragma unroll
            for (int half = 0; half < 2; half++) {
                int row = r0 + half * 8;
                float v0 = acc[mt][nt][half * 2 + 0] + bias[c0];
                float v1 = acc[mt][nt][half * 2 + 1] + bias[c0 + 1];
                if (EPI == 1) { v0 = fmaxf(v0, 0.f); v1 = fmaxf(v1, 0.f); }
                if (STORE == 0) {
                    *(float2*)(C + (size_t)row * ldc + c0) = make_float2(v0, v1);
                } else {
                    *(uint32_t*)(Co + (size_t)row * ldc + c0) =
                        hpk2(__float2half_rn(v0), __float2half_rn(v1));
                }
            }
        }
    }
}

// ======== FUSED FLASH ATTENTION (plain fp16) =================================
__global__ void __launch_bounds__(256, 1) flash_kernel(
    const fp16* __restrict__ Qs_, const fp16* __restrict__ Kb_,
    const fp16* __restrict__ Vt_,
    const float* __restrict__ qrel, const float* __restrict__ rel_v,
    fp16* __restrict__ AT)
{
    constexpr int uQ = 0, uK = 18432, uV = 55296;
    constexpr int uQR = 90112, uBAND = 107520, uRV = 124416, uSTAT = 132864;
    extern __shared__ __align__(16) char dsm[];
    uint32_t ub = smem_u32(dsm);
    float* qrel_s = (float*)(dsm + uQR);    // [128][34]
    float* band_s = (float*)(dsm + uBAND);  // [128][33]
    float* relv_s = (float*)(dsm + uRV);    // [33][64]
    float* stat_s = (float*)(dsm + uSTAT);  // [128][2]

    int tid = threadIdx.x, wid = tid >> 5, lane = tid & 31;
    int qi = blockIdx.x, bh = blockIdx.y;
    int bB = bh >> 4, hh = bh & 15;

    size_t qkbase = (size_t)bB * (LL * DD) + hh * DKK;
    size_t vbase  = (size_t)bh * (DKK * LL);

#define FISSUE_KV(t, st) do {                                                  \
    _Pragma("unroll") for (int i_ = 0; i_ < 4; i_++) {                         \
        int id_ = i_ * 256 + tid; int r_ = id_ >> 3, c_ = id_ & 7;             \
        cpa16(ub + uK + (st) * 18432 + r_ * 144 + c_ * 16,                     \
              Kb_ + qkbase + (size_t)((t) * 128 + r_) * 1024 + c_ * 8);        \
    }                                                                          \
    _Pragma("unroll") for (int i_ = 0; i_ < 4; i_++) {                         \
        int id_ = i_ * 256 + tid; int r_ = id_ >> 4, c_ = id_ & 15;            \
        cpa16(ub + uV + (st) * 17408 + r_ * 272 + c_ * 16,                     \
              Vt_ + vbase + (size_t)r_ * 1024 + (t) * 128 + c_ * 8);           \
    }                                                                          \
} while (0)

#pragma unroll
    for (int i = 0; i < 4; i++) {
        int id = i * 256 + tid; int r = id >> 3, c = id & 7;
        cpa16(ub + uQ + r * 144 + c * 16, Qs_ + qkbase + (size_t)(qi * 128 + r) * 1024 + c * 8);
    }
    FISSUE_KV(0, 0);
    CP_COMMIT();
    FISSUE_KV(1, 1);
    CP_COMMIT();

    for (int idx = tid; idx < 128 * 33; idx += 256) {
        int r = idx / 33, j = idx - r * 33;
        qrel_s[r * 34 + j] = qrel[((size_t)(bB * 1024 + qi * 128 + r) * 16 + hh) * 33 + j];
        band_s[r * 33 + j] = -1e30f;
    }
    for (int idx = tid; idx < 33 * 64; idx += 256) relv_s[idx] = rel_v[idx];

    CP_WAIT1();
    __syncthreads();

    uint32_t qA[4][4];
    {
        uint32_t ar = (wid << 4) + (lane & 15);
#pragma unroll
        for (int ks = 0; ks < 4; ks++) {
            uint32_t ac = ks * 16 + ((lane >> 4) << 3);
            ldsm4(qA[ks], ub + uQ + ar * 144 + ac * 2);
        }
    }

    int lrow0 = (wid << 4) + (lane >> 2), lrow1 = lrow0 + 8;
    int rowg0 = qi * 128 + lrow0, rowg1 = rowg0 + 8;
    float qw0_0  = qrel_s[lrow0 * 34 + 0],  qw32_0 = qrel_s[lrow0 * 34 + 32];
    float qw0_1  = qrel_s[lrow1 * 34 + 0],  qw32_1 = qrel_s[lrow1 * 34 + 32];

    float m0 = -1e30f, m1 = -1e30f, l0 = 0.f, l1 = 0.f;
    float sL0 = 0.f, sL1 = 0.f, sR0 = 0.f, sR1 = 0.f;
    float accO[8][4];
#pragma unroll
    for (int nt = 0; nt < 8; nt++)
#pragma unroll
        for (int i = 0; i < 4; i++) accO[nt][i] = 0.f;

    for (int ki = 0; ki < 8; ki++) {
        int st = ki & 1;
        if (ki > 0) {
            if (ki == 7) CP_WAIT0(); else CP_WAIT1();
            __syncthreads();
        }

        // ---- S = Q K^T
        float accS[16][4];
#pragma unroll
        for (int nt = 0; nt < 16; nt++)
#pragma unroll
            for (int i = 0; i < 4; i++) accS[nt][i] = 0.f;
#pragma unroll
        for (int ks = 0; ks < 4; ks++) {
#pragma unroll
            for (int p = 0; p < 8; p++) {
                uint32_t br = p * 16 + ((lane >> 4) << 3) + (lane & 7);
                uint32_t bc = ks * 16 + (((lane >> 3) & 1) << 3);
                uint32_t rh[4];
                ldsm4(rh, ub + uK + st * 18432 + br * 144 + bc * 2);
                uint32_t b0h[2] = {rh[0], rh[1]}, b1h[2] = {rh[2], rh[3]};
                mmaf16(accS[2*p],     qA[ks], b0h);
                mmaf16(accS[2*p + 1], qA[ks], b1h);
            }
        }

        bool band_tile = (ki >= qi - 1) && (ki <= qi + 1);
        float tmax0 = -1e30f, tmax1 = -1e30f;
        if (!band_tile) {
            float qa0 = (ki < qi) ? qw0_0 : qw32_0;
            float qa1 = (ki < qi) ? qw0_1 : qw32_1;
#pragma unroll
            for (int nt = 0; nt < 16; nt++) {
                accS[nt][0] = (accS[nt][0] + qa0) * 0.125f;
                accS[nt][1] = (accS[nt][1] + qa0) * 0.125f;
                accS[nt][2] = (accS[nt][2] + qa1) * 0.125f;
                accS[nt][3] = (accS[nt][3] + qa1) * 0.125f;
                tmax0 = fmaxf(tmax0, fmaxf(accS[nt][0], accS[nt][1]));
                tmax1 = fmaxf(tmax1, fmaxf(accS[nt][2], accS[nt][3]));
            }
        } else {
#pragma unroll
            for (int nt = 0; nt < 16; nt++) {
#pragma unroll
                for (int e = 0; e < 4; e++) {
                    int colg = ki * 128 + nt * 8 + ((lane & 3) << 1) + (e & 1);
                    int rg   = (e < 2) ? rowg0 : rowg1;
                    int lr   = (e < 2) ? lrow0 : lrow1;
                    int d = colg - rg;
                    float qr;
                    if (d < -16)      qr = (e < 2) ? qw0_0  : qw0_1;
                    else if (d > 16)  qr = (e < 2) ? qw32_0 : qw32_1;
                    else              qr = qrel_s[lr * 34 + d + 16];
                    float s = (accS[nt][e] + qr) * 0.125f;
                    if (d >= -16 && d <= 16) band_s[lr * 33 + d + 16] = s;
                    accS[nt][e] = s;
                    if (e < 2) tmax0 = fmaxf(tmax0, s); else tmax1 = fmaxf(tmax1, s);
                }
            }
        }
        tmax0 = fmaxf(tmax0, __shfl_xor_sync(0xffffffffu, tmax0, 1));
        tmax0 = fmaxf(tmax0, __shfl_xor_sync(0xffffffffu, tmax0, 2));
        tmax1 = fmaxf(tmax1, __shfl_xor_sync(0xffffffffu, tmax1, 1));
        tmax1 = fmaxf(tmax1, __shfl_xor_sync(0xffffffffu, tmax1, 2));

        float mn0 = fmaxf(m0, tmax0), mn1 = fmaxf(m1, tmax1);
        float sc0 = __expf(m0 - mn0), sc1 = __expf(m1 - mn1);
        m0 = mn0; m1 = mn1;
        l0 *= sc0; sL0 *= sc0; sR0 *= sc0;
        l1 *= sc1; sL1 *= sc1; sR1 *= sc1;
#pragma unroll
        for (int nt = 0; nt < 8; nt++) {
            accO[nt][0] *= sc0; accO[nt][1] *= sc0;
            accO[nt][2] *= sc1; accO[nt][3] *= sc1;
        }

        float es0 = 0.f, es1 = 0.f, eL0 = 0.f, eL1 = 0.f, eR0 = 0.f, eR1 = 0.f;
        if (!band_tile) {
#pragma unroll
            for (int nt = 0; nt < 16; nt++) {
                float e0 = __expf(accS[nt][0] - m0); accS[nt][0] = e0;
                float e1 = __expf(accS[nt][1] - m0); accS[nt][1] = e1;
                float e2 = __expf(accS[nt][2] - m1); accS[nt][2] = e2;
                float e3 = __expf(accS[nt][3] - m1); accS[nt][3] = e3;
                es0 += e0 + e1; es1 += e2 + e3;
            }
            if (ki < qi) { eL0 = es0; eL1 = es1; }
            else         { eR0 = es0; eR1 = es1; }
        } else {
#pragma unroll
            for (int nt = 0; nt < 16; nt++) {
#pragma unroll
                for (int e = 0; e < 4; e++) {
                    int colg = ki * 128 + nt * 8 + ((lane & 3) << 1) + (e & 1);
                    int rg = (e < 2) ? rowg0 : rowg1;
                    int d = colg - rg;
                    float mm = (e < 2) ? m0 : m1;
                    float ev = __expf(accS[nt][e] - mm);
                    accS[nt][e] = ev;
                    if (e < 2) {
                        es0 += ev;
                        if (d < -16) eL0 += ev; else if (d > 16) eR0 += ev;
                    } else {
                        es1 += ev;
                        if (d < -16) eL1 += ev; else if (d > 16) eR1 += ev;
                    }
                }
            }
        }
#pragma unroll
        for (int o = 1; o <= 2; o <<= 1) {
            es0 += __shfl_xor_sync(0xffffffffu, es0, o);
            es1 += __shfl_xor_sync(0xffffffffu, es1, o);
            eL0 += __shfl_xor_sync(0xffffffffu, eL0, o);
            eL1 += __shfl_xor_sync(0xffffffffu, eL1, o);
            eR0 += __shfl_xor_sync(0xffffffffu, eR0, o);
            eR1 += __shfl_xor_sync(0xffffffffu, eR1, o);
        }
        l0 += es0; sL0 += eL0; sR0 += eR0;
        l1 += es1; sL1 += eL1; sR1 += eR1;

        // ---- pack P as fp16 in A-fragment order
        uint32_t ph[16][2];
#pragma unroll
        for (int nt = 0; nt < 16; nt++) {
            ph[nt][0] = hpk2(__float2half_rn(accS[nt][0]), __float2half_rn(accS[nt][1]));
            ph[nt][1] = hpk2(__float2half_rn(accS[nt][2]), __float2half_rn(accS[nt][3]));
        }

        // ---- O += P V
#pragma unroll
        for (int ks2 = 0; ks2 < 8; ks2++) {
            uint32_t aH[4] = { ph[2*ks2][0], ph[2*ks2][1], ph[2*ks2+1][0], ph[2*ks2+1][1] };
#pragma unroll
            for (int p = 0; p < 4; p++) {
                uint32_t br = p * 16 + ((lane >> 4) << 3) + (lane & 7);
                uint32_t bc = ks2 * 16 + (((lane >> 3) & 1) << 3);
                uint32_t rh[4];
                ldsm4(rh, ub + uV + st * 17408 + br * 272 + bc * 2);
                uint32_t b0h[2] = {rh[0], rh[1]}, b1h[2] = {rh[2], rh[3]};
                mmaf16(accO[2*p],     aH, b0h);
                mmaf16(accO[2*p + 1], aH, b1h);
            }
        }

        __syncthreads();
        if (ki < 6) { FISSUE_KV(ki + 2, st); CP_COMMIT(); }
    }
#undef FISSUE_KV

    if ((lane & 3) == 0) {
        stat_s[lrow0 * 2] = m0; stat_s[lrow0 * 2 + 1] = l0;
        stat_s[lrow1 * 2] = m1; stat_s[lrow1 * 2 + 1] = l1;
    }
    __syncthreads();
    if (tid < 128) {
        float mm = stat_s[tid * 2], invl = 1.f / stat_s[tid * 2 + 1];
#pragma unroll
        for (int j = 0; j < 33; j++)
            band_s[tid * 33 + j] = __expf(band_s[tid * 33 + j] - mm) * invl;
    }
    __syncthreads();

    float inv0 = 1.f / l0, inv1 = 1.f / l1;
    float pa0 = sL0 * inv0, pb0 = sR0 * inv0;
    float pa1 = sL1 * inv1, pb1 = sR1 * inv1;
#pragma unroll
    for (int nt = 0; nt < 8; nt++) {
        int c0 = nt * 8 + ((lane & 3) << 1);
        accO[nt][0] = accO[nt][0] * inv0 + pa0 * relv_s[c0]     + pb0 * relv_s[32*64 + c0];
        accO[nt][1] = accO[nt][1] * inv0 + pa0 * relv_s[c0 + 1] + pb0 * relv_s[32*64 + c0 + 1];
        accO[nt][2] = accO[nt][2] * inv1 + pa1 * relv_s[c0]     + pb1 * relv_s[32*64 + c0];
        accO[nt][3] = accO[nt][3] * inv1 + pa1 * relv_s[c0 + 1] + pb1 * relv_s[32*64 + c0 + 1];
    }
#pragma unroll
    for (int j = 0; j < 33; j++) {
        float bp0 = band_s[lrow0 * 33 + j];
        float bp1 = band_s[lrow1 * 33 + j];
        const float* rv = relv_s + j * 64;
#pragma unroll
        for (int nt = 0; nt < 8; nt++) {
            int c0 = nt * 8 + ((lane & 3) << 1);
            float r0 = rv[c0], r1 = rv[c0 + 1];
            accO[nt][0] += bp0 * r0; accO[nt][1] += bp0 * r1;
            accO[nt][2] += bp1 * r0; accO[nt][3] += bp1 * r1;
        }
    }

    size_t obase = (size_t)(bB * 1024 + qi * 128) * 1024 + hh * 64;
#pragma unroll
    for (int nt = 0; nt < 8; nt++) {
        int c0 = nt * 8 + ((lane & 3) << 1);
        *(uint32_t*)(AT + obase + (size_t)lrow0 * 1024 + c0) =
            hpk2(__float2half_rn(accO[nt][0]), __float2half_rn(accO[nt][1]));
        *(uint32_t*)(AT + obase + (size_t)lrow1 * 1024 + c0) =
            hpk2(__float2half_rn(accO[nt][2]), __float2half_rn(accO[nt][3]));
    }
}

// ---------------- W [K,N] fp32 -> Wt [N,K] fp16 -------------------------------
__global__ void convert_wt_kernel(const float* __restrict__ W, fp16* __restrict__ o,
                                  int K, int N)
{
    __shared__ float t[32][33];
    int n0 = blockIdx.x * 32, k0 = blockIdx.y * 32;
    int tx = threadIdx.x, ty = threadIdx.y;
    for (int i = ty; i < 32; i += 8)
        t[i][tx] = W[(size_t)(k0 + i) * N + n0 + tx];
    __syncthreads();
    for (int i = ty; i < 32; i += 8)
        o[(size_t)(n0 + i) * K + k0 + tx] = __float2half_rn(t[tx][i]);
}

// ---------------- fused q/k/v fp32 -> fp16 ------------------------------------
__global__ void split3_kernel(const float* __restrict__ q, const float* __restrict__ k,
                              const float* __restrict__ v,
                              fp16* __restrict__ qo, fp16* __restrict__ ko, fp16* __restrict__ vo)
{
    const float* X = (blockIdx.y == 0) ? q : (blockIdx.y == 1) ? k : v;
    fp16* O = (blockIdx.y == 0) ? qo : (blockIdx.y == 1) ? ko : vo;
    size_t i = ((size_t)blockIdx.x * 256 + threadIdx.x) * 4;
    float4 w = *(const float4*)(X + i);
    *(uint2*)(O + i) = make_uint2(hpk2(__float2half_rn(w.x), __float2half_rn(w.y)),
                                  hpk2(__float2half_rn(w.z), __float2half_rn(w.w)));
}

// ---------------- V: [b,l,h*64+d] fp16 -> Vt [bh][d][l] fp16 ------------------
__global__ void transpose_v(const fp16* __restrict__ V, fp16* __restrict__ o)
{
    __shared__ fp16 t[32][34];
    int bh = blockIdx.z; int b = bh >> 4, h = bh & 15;
    int l0 = blockIdx.x * 32, d0 = blockIdx.y * 32;
    for (int i = threadIdx.y; i < 32; i += 8)
        t[i][threadIdx.x] = V[(size_t)(b * LL + l0 + i) * DD + h * DKK + d0 + threadIdx.x];
    __syncthreads();
    for (int i = threadIdx.y; i < 32; i += 8)
        o[((size_t)bh * DKK + d0 + i) * LL + l0 + threadIdx.x] = t[threadIdx.x][i];
}

// ---------------- qrel[b,l,h,r] = Qh[b,l,h,:] . rel_k[r,:] --------------------
__global__ void qrel_kernel(const fp16* __restrict__ Q, const float* __restrict__ rel_k,
                            float* __restrict__ qrel)
{
    __shared__ float rk[NREL * DKK];
    int t = threadIdx.x;
    for (int i = t; i < NREL * DKK; i += 256) rk[i] = rel_k[i];
    __syncthreads();
    int w = t >> 5, lane = t & 31;
    int item = blockIdx.x * 8 + w;
    int bl = item >> 4, h = item & 15;
    size_t i0 = (size_t)bl * DD + h * DKK + lane * 2;
    float q0 = __half2float(Q[i0]);
    float q1 = __half2float(Q[i0 + 1]);
    for (int r = 0; r < NREL; r++) {
        float v = q0 * rk[r * DKK + lane * 2] + q1 * rk[r * DKK + lane * 2 + 1];
        v += __shfl_xor_sync(0xffffffffu, v, 16);
        v += __shfl_xor_sync(0xffffffffu, v, 8);
        v += __shfl_xor_sync(0xffffffffu, v, 4);
        v += __shfl_xor_sync(0xffffffffu, v, 2);
        v += __shfl_xor_sync(0xffffffffu, v, 1);
        if (lane == 0) qrel[(size_t)item * NREL + r] = v;
    }
}

// ---------------- residual add + layernorm (vectorized) -----------------------
__global__ void ln_kernel(const float* __restrict__ X, const float* __restrict__ R,
                          const float* __restrict__ g, const float* __restrict__ be,
                          float* __restrict__ out, fp16* __restrict__ oh)
{
    int row = blockIdx.x, t = threadIdx.x;
    __shared__ float red[256];
    float4 v = *(const float4*)(X + (size_t)row * DD + t * 4);
    float4 r4 = *(const float4*)(R + (size_t)row * DD + t * 4);
    v.x += r4.x; v.y += r4.y; v.z += r4.z; v.w += r4.w;
    float s1 = v.x + v.y + v.z + v.w;
    red[t] = s1; __syncthreads();
    for (int s = 128; s > 0; s >>= 1) { if (t < s) red[t] += red[t + s]; __syncthreads(); }
    float mu = red[0] * (1.f / 1024.f);
    __syncthreads();
    float dx = v.x - mu, dy = v.y - mu, dz = v.z - mu, dw = v.w - mu;
    red[t] = dx * dx + dy * dy + dz * dz + dw * dw; __syncthreads();
    for (int s = 128; s > 0; s >>= 1) { if (t < s) red[t] += red[t + s]; __syncthreads(); }
    float rstd = rsqrtf(red[0] * (1.f / 1024.f) + 1e-6f);
    float4 g4 = *(const float4*)(g + t * 4);
    float4 b4 = *(const float4*)(be + t * 4);
    float4 o4;
    o4.x = dx * rstd * g4.x + b4.x;
    o4.y = dy * rstd * g4.y + b4.y;
    o4.z = dz * rstd * g4.z + b4.z;
    o4.w = dw * rstd * g4.w + b4.w;
    *(float4*)(out + (size_t)row * DD + t * 4) = o4;
    if (oh) {
        *(uint2*)(oh + (size_t)row * DD + t * 4) =
            make_uint2(hpk2(__float2half_rn(o4.x), __float2half_rn(o4.y)),
                       hpk2(__float2half_rn(o4.z), __float2half_rn(o4.w)));
    }
}

// ---------------- launch ------------------------------------------------------
extern "C" void kernel_launch(void* const* d_in, const int* in_sizes, int n_in,
                              void* d_out, int out_size)
{
    const float* q    = (const float*)d_in[0];
    const float* k    = (const float*)d_in[1];
    const float* v    = (const float*)d_in[2];
    const float* wq   = (const float*)d_in[3];
    const float* bq   = (const float*)d_in[4];
    const float* wk   = (const float*)d_in[5];
    const float* bk   = (const float*)d_in[6];
    const float* wv   = (const float*)d_in[7];
    const float* bv   = (const float*)d_in[8];
    const float* wfc  = (const float*)d_in[9];
    const float* bfc  = (const float*)d_in[10];
    const float* w1   = (const float*)d_in[11];
    const float* b1   = (const float*)d_in[12];
    const float* w2   = (const float*)d_in[13];
    const float* b2   = (const float*)d_in[14];
    const float* ln_g = (const float*)d_in[15];
    const float* ln_b = (const float*)d_in[16];
    const float* rel_k= (const float*)d_in[17];
    const float* rel_v= (const float*)d_in[18];
    float* out = (float*)d_out;

    float *gqrel, *gfc, *gx1, *gy;
    cudaGetSymbolAddress((void**)&gqrel, g_qrel);
    cudaGetSymbolAddress((void**)&gfc, g_fc);
    cudaGetSymbolAddress((void**)&gx1, g_x1);
    cudaGetSymbolAddress((void**)&gy, g_y);

    fp16 *wqt,*wkt,*wvt,*wft,*w1t,*w2t,*qs,*ks,*vs,*Qs,*Kb,*Vp,*Vt,*AT,*x1s,*hid;
    cudaGetSymbolAddress((void**)&wqt, g_wqt);
    cudaGetSymbolAddress((void**)&wkt, g_wkt);
    cudaGetSymbolAddress((void**)&wvt, g_wvt);
    cudaGetSymbolAddress((void**)&wft, g_wft);
    cudaGetSymbolAddress((void**)&w1t, g_w1t);
    cudaGetSymbolAddress((void**)&w2t, g_w2t);
    cudaGetSymbolAddress((void**)&qs, g_qs);
    cudaGetSymbolAddress((void**)&ks, g_ks);
    cudaGetSymbolAddress((void**)&vs, g_vs);
    cudaGetSymbolAddress((void**)&Qs, g_Qs);
    cudaGetSymbolAddress((void**)&Kb, g_Kb);
    cudaGetSymbolAddress((void**)&Vp, g_Vp);
    cudaGetSymbolAddress((void**)&Vt, g_Vt);
    cudaGetSymbolAddress((void**)&AT, g_AT);
    cudaGetSymbolAddress((void**)&x1s, g_x1s);
    cudaGetSymbolAddress((void**)&hid, g_hid);

    const int SMG = 3 * 36864;       // 110592 B per CTA (2 CTAs/SM)
    const int SMFLASH = 133888;
    cudaFuncSetAttribute(hgemm<0,0>, cudaFuncAttributeMaxDynamicSharedMemorySize, SMG);
    cudaFuncSetAttribute(hgemm<0,1>, cudaFuncAttributeMaxDynamicSharedMemorySize, SMG);
    cudaFuncSetAttribute(hgemm<1,1>, cudaFuncAttributeMaxDynamicSharedMemorySize, SMG);
    cudaFuncSetAttribute(flash_kernel, cudaFuncAttributeMaxDynamicSharedMemorySize, SMFLASH);

    // prep
    split3_kernel<<<dim3(MTOK*DD/1024, 3), 256>>>(q, k, v, qs, ks, vs);
    convert_wt_kernel<<<dim3(32,32),  dim3(32,8)>>>(wq,  wqt, DD, DD);
    convert_wt_kernel<<<dim3(32,32),  dim3(32,8)>>>(wk,  wkt, DD, DD);
    convert_wt_kernel<<<dim3(32,32),  dim3(32,8)>>>(wv,  wvt, DD, DD);

    // projections
    hgemm<0,1><<<dim3(8,64),128,SMG>>>(qs, wqt, bq, nullptr, Qs, DD, DD, DD, DD);
    hgemm<0,1><<<dim3(8,64),128,SMG>>>(ks, wkt, bk, nullptr, Kb, DD, DD, DD, DD);
    hgemm<0,1><<<dim3(8,64),128,SMG>>>(vs, wvt, bv, nullptr, Vp, DD, DD, DD, DD);

    // remaining weight converts + V repack + qrel
    convert_wt_kernel<<<dim3(32,32),  dim3(32,8)>>>(wfc, wft, DD, DD);
    convert_wt_kernel<<<dim3(128,32), dim3(32,8)>>>(w1, w1t, DD, DI);
    convert_wt_kernel<<<dim3(32,128), dim3(32,8)>>>(w2, w2t, DI, DD);
    transpose_v<<<dim3(32,2,BB*HH), dim3(32,8)>>>(Vp, Vt);
    qrel_kernel<<<MTOK*HH/8, 256>>>(Qs, rel_k, gqrel);

    // fused attention -> AT (fp16)
    flash_kernel<<<dim3(8, BB*HH), 256, SMFLASH>>>(Qs, Kb, Vt, gqrel, rel_v, AT);

    // fc + residual(q) + LN
    hgemm<0,0><<<dim3(8,64),128,SMG>>>(AT, wft, bfc, gfc, nullptr, DD, DD, DD, DD);
    ln_kernel<<<MTOK,256>>>(gfc, q, ln_g, ln_b, gx1, x1s);

    // FFN + residual + LN -> out
    hgemm<1,1><<<dim3(32,64),128,SMG>>>(x1s, w1t, b1, nullptr, hid, DD, DD, DD, DI);
    hgemm<0,0><<<dim3(8,64),128,SMG>>>(hid, w2t, b2, gy, nullptr, DI, DI, DI, DD);
    ln_kernel<<<MTOK,256>>>(gy, gx1, ln_g, ln_b, out, nullptr);
}

// round 17
// speedup vs baseline: 1.5436x; 1.5436x over previous
#include <cuda_runtime.h>
#include <cuda_fp16.h>
#include <cstdint>

#define BB 8
#define LL 1024
#define DD 1024
#define HH 16
#define DKK 64
#define DI 4096
#define MTOK (BB*LL)
#define NREL 33

using fp16 = __half;

// ---------------- scratch (device globals) -----------------------------------
__device__ float g_qrel[(size_t)MTOK*HH*NREL];
__device__ float g_fc[MTOK*DD];
__device__ float g_x1[MTOK*DD];
__device__ float g_y[MTOK*DD];

__device__ fp16 g_wqt[DD*DD];
__device__ fp16 g_wkt[DD*DD];
__device__ fp16 g_wvt[DD*DD];
__device__ fp16 g_wft[DD*DD];
__device__ fp16 g_w1t[(size_t)DI*DD];
__device__ fp16 g_w2t[(size_t)DD*DI];
__device__ fp16 g_qs[MTOK*DD];
__device__ fp16 g_ks[MTOK*DD];
__device__ fp16 g_vs[MTOK*DD];
__device__ fp16 g_Qs[MTOK*DD];
__device__ fp16 g_Kb[MTOK*DD];
__device__ fp16 g_Vp[MTOK*DD];
__device__ fp16 g_Vt[BB*HH*DKK*LL];
__device__ fp16 g_AT[MTOK*DD];
__device__ fp16 g_x1s[MTOK*DD];
__device__ fp16 g_hid[(size_t)MTOK*DI];

// ---------------- helpers -----------------------------------------------------
__device__ __forceinline__ uint32_t smem_u32(const void* p) {
    uint32_t a;
    asm("{ .reg .u64 t; cvta.to.shared.u64 t, %1; cvt.u32.u64 %0, t; }" : "=r"(a) : "l"(p));
    return a;
}
__device__ __forceinline__ uint32_t hpk2(fp16 a, fp16 b) {
    __half2 t = __halves2half2(a, b);
    return *reinterpret_cast<uint32_t*>(&t);
}
__device__ __forceinline__ void ldsm4(uint32_t* r, uint32_t addr) {
    asm volatile("ldmatrix.sync.aligned.m8n8.x4.shared.b16 {%0,%1,%2,%3}, [%4];"
                 : "=r"(r[0]), "=r"(r[1]), "=r"(r[2]), "=r"(r[3]) : "r"(addr));
}
__device__ __forceinline__ void mmaf16(float* d, const uint32_t* a, const uint32_t* b) {
    asm volatile("mma.sync.aligned.m16n8k16.row.col.f32.f16.f16.f32 "
                 "{%0,%1,%2,%3}, {%4,%5,%6,%7}, {%8,%9}, {%0,%1,%2,%3};"
                 : "+f"(d[0]), "+f"(d[1]), "+f"(d[2]), "+f"(d[3])
                 : "r"(a[0]), "r"(a[1]), "r"(a[2]), "r"(a[3]), "r"(b[0]), "r"(b[1]));
}
__device__ __forceinline__ void cpa16(uint32_t s, const void* g) {
    asm volatile("cp.async.cg.shared.global [%0], [%1], 16;" :: "r"(s), "l"(g));
}
#define CP_COMMIT() asm volatile("cp.async.commit_group;" ::: "memory")
#define CP_WAIT1()  asm volatile("cp.async.wait_group 1;" ::: "memory")
#define CP_WAIT0()  asm volatile("cp.async.wait_group 0;" ::: "memory")

// ======== fp16 GEMM: block 128x128, 8 warps (warp 64x32), BK=64, 3-stage ======
// 2 CTA/SM (16 warps/SM), ONE barrier per K-tile.  [round-14 proven config]
// EPI: 0 = +bias, 1 = +bias,relu   STORE: 0 = fp32 C, 1 = fp16 Co
template<int EPI, int STORE>
__global__ void __launch_bounds__(256, 2) hgemm(
    const fp16* __restrict__ A, const fp16* __restrict__ B,
    const float* __restrict__ bias, float* __restrict__ C,
    fp16* __restrict__ Co,
    int K, int lda, int ldb, int ldc)
{
    constexpr int SS = 36864;   // stage: A 128x144B | B 128x144B
    extern __shared__ __align__(16) char dsm[];
    uint32_t ub = smem_u32(dsm);

    int tid = threadIdx.x, wid = tid >> 5, lane = tid & 31;
    int brow = blockIdx.y * 128;
    int bcol = blockIdx.x * 128;
    int wm = (wid & 1) * 64;
    int wn = (wid >> 1) * 32;

    float acc[4][4][4];
#pragma unroll
    for (int mt = 0; mt < 4; mt++)
#pragma unroll
        for (int nt = 0; nt < 4; nt++)
#pragma unroll
            for (int i = 0; i < 4; i++) acc[mt][nt][i] = 0.f;

    const int KT = K >> 6;

#define ISSUE(stg, k0) do {                                                       \
    uint32_t us_ = ub + (stg) * SS;                                               \
    _Pragma("unroll")                                                             \
    for (int i_ = 0; i_ < 4; i_++) {                                              \
        int id_ = i_ * 256 + tid; int r_ = id_ >> 3, c_ = id_ & 7;                \
        cpa16(us_ + r_ * 144 + c_ * 16,                                           \
              A + (size_t)(brow + r_) * lda + (k0) + c_ * 8);                     \
    }                                                                             \
    _Pragma("unroll")                                                             \
    for (int i_ = 0; i_ < 4; i_++) {                                              \
        int id_ = i_ * 256 + tid; int r_ = id_ >> 3, c_ = id_ & 7;                \
        cpa16(us_ + 18432 + r_ * 144 + c_ * 16,                                   \
              B + (size_t)(bcol + r_) * ldb + (k0) + c_ * 8);                     \
    }                                                                             \
} while (0)

    int fetch = 0;
    const int PRE = (2 < KT) ? 2 : KT;
    for (; fetch < PRE; fetch++) { ISSUE(fetch, fetch << 6); CP_COMMIT(); }

    for (int kt = 0; kt < KT; kt++) {
        if (kt == KT - 1) CP_WAIT0(); else CP_WAIT1();
        __syncthreads();                       // also protects stage (kt+2)%3 reuse
        if (fetch < KT) { ISSUE(fetch % 3, fetch << 6); CP_COMMIT(); fetch++; }

        uint32_t us = ub + (kt % 3) * SS;
#pragma unroll
        for (int ks = 0; ks < 4; ks++) {
            uint32_t aH[4][4], bH[4][2];
#pragma unroll
            for (int mt = 0; mt < 4; mt++) {
                uint32_t ar = wm + mt * 16 + (lane & 15);
                uint32_t ac = ks * 16 + ((lane >> 4) << 3);
                ldsm4(aH[mt], us + ar * 144 + ac * 2);
            }
#pragma unroll
            for (int p = 0; p < 2; p++) {
                uint32_t br = wn + p * 16 + ((lane >> 4) << 3) + (lane & 7);
                uint32_t bc = ks * 16 + (((lane >> 3) & 1) << 3);
                uint32_t r[4];
                ldsm4(r, us + 18432 + br * 144 + bc * 2);
                bH[p * 2][0] = r[0]; bH[p * 2][1] = r[1];
                bH[p * 2 + 1][0] = r[2]; bH[p * 2 + 1][1] = r[3];
            }
#pragma unroll
            for (int mt = 0; mt < 4; mt++)
#pragma unroll
                for (int nt = 0; nt < 4; nt++)
                    mmaf16(acc[mt][nt], aH[mt], bH[nt]);
        }
        // no trailing barrier: next iteration's top barrier covers the hazard
    }
#undef ISSUE

    // epilogue
#pragma unroll
    for (int mt = 0; mt < 4; mt++) {
#pragma unroll
        for (int nt = 0; nt < 4; nt++) {
            int r0 = brow + wm + mt * 16 + (lane >> 2);
            int c0 = bcol + wn + nt * 8 + ((lane & 3) << 1);
#pragma unroll
            for (int half = 0; half < 2; half++) {
                int row = r0 + half * 8;
                float v0 = acc[mt][nt][half * 2 + 0] + bias[c0];
                float v1 = acc[mt][nt][half * 2 + 1] + bias[c0 + 1];
                if (EPI == 1) { v0 = fmaxf(v0, 0.f); v1 = fmaxf(v1, 0.f); }
                if (STORE == 0) {
                    *(float2*)(C + (size_t)row * ldc + c0) = make_float2(v0, v1);
                } else {
                    *(uint32_t*)(Co + (size_t)row * ldc + c0) =
                        hpk2(__float2half_rn(v0), __float2half_rn(v1));
                }
            }
        }
    }
}

// ======== FUSED FLASH ATTENTION (plain fp16) =================================
__global__ void __launch_bounds__(256, 1) flash_kernel(
    const fp16* __restrict__ Qs_, const fp16* __restrict__ Kb_,
    const fp16* __restrict__ Vt_,
    const float* __restrict__ qrel, const float* __restrict__ rel_v,
    fp16* __restrict__ AT)
{
    constexpr int uQ = 0, uK = 18432, uV = 55296;
    constexpr int uQR = 90112, uBAND = 107520, uRV = 124416, uSTAT = 132864;
    extern __shared__ __align__(16) char dsm[];
    uint32_t ub = smem_u32(dsm);
    float* qrel_s = (float*)(dsm + uQR);    // [128][34]
    float* band_s = (float*)(dsm + uBAND);  // [128][33]
    float* relv_s = (float*)(dsm + uRV);    // [33][64]
    float* stat_s = (float*)(dsm + uSTAT);  // [128][2]

    int tid = threadIdx.x, wid = tid >> 5, lane = tid & 31;
    int qi = blockIdx.x, bh = blockIdx.y;
    int bB = bh >> 4, hh = bh & 15;

    size_t qkbase = (size_t)bB * (LL * DD) + hh * DKK;
    size_t vbase  = (size_t)bh * (DKK * LL);

#define FISSUE_KV(t, st) do {                                                  \
    _Pragma("unroll") for (int i_ = 0; i_ < 4; i_++) {                         \
        int id_ = i_ * 256 + tid; int r_ = id_ >> 3, c_ = id_ & 7;             \
        cpa16(ub + uK + (st) * 18432 + r_ * 144 + c_ * 16,                     \
              Kb_ + qkbase + (size_t)((t) * 128 + r_) * 1024 + c_ * 8);        \
    }                                                                          \
    _Pragma("unroll") for (int i_ = 0; i_ < 4; i_++) {                         \
        int id_ = i_ * 256 + tid; int r_ = id_ >> 4, c_ = id_ & 15;            \
        cpa16(ub + uV + (st) * 17408 + r_ * 272 + c_ * 16,                     \
              Vt_ + vbase + (size_t)r_ * 1024 + (t) * 128 + c_ * 8);           \
    }                                                                          \
} while (0)

#pragma unroll
    for (int i = 0; i < 4; i++) {
        int id = i * 256 + tid; int r = id >> 3, c = id & 7;
        cpa16(ub + uQ + r * 144 + c * 16, Qs_ + qkbase + (size_t)(qi * 128 + r) * 1024 + c * 8);
    }
    FISSUE_KV(0, 0);
    CP_COMMIT();
    FISSUE_KV(1, 1);
    CP_COMMIT();

    for (int idx = tid; idx < 128 * 33; idx += 256) {
        int r = idx / 33, j = idx - r * 33;
        qrel_s[r * 34 + j] = qrel[((size_t)(bB * 1024 + qi * 128 + r) * 16 + hh) * 33 + j];
        band_s[r * 33 + j] = -1e30f;
    }
    for (int idx = tid; idx < 33 * 64; idx += 256) relv_s[idx] = rel_v[idx];

    CP_WAIT1();
    __syncthreads();

    uint32_t qA[4][4];
    {
        uint32_t ar = (wid << 4) + (lane & 15);
#pragma unroll
        for (int ks = 0; ks < 4; ks++) {
            uint32_t ac = ks * 16 + ((lane >> 4) << 3);
            ldsm4(qA[ks], ub + uQ + ar * 144 + ac * 2);
        }
    }

    int lrow0 = (wid << 4) + (lane >> 2), lrow1 = lrow0 + 8;
    int rowg0 = qi * 128 + lrow0, rowg1 = rowg0 + 8;
    float qw0_0  = qrel_s[lrow0 * 34 + 0],  qw32_0 = qrel_s[lrow0 * 34 + 32];
    float qw0_1  = qrel_s[lrow1 * 34 + 0],  qw32_1 = qrel_s[lrow1 * 34 + 32];

    float m0 = -1e30f, m1 = -1e30f, l0 = 0.f, l1 = 0.f;
    float sL0 = 0.f, sL1 = 0.f, sR0 = 0.f, sR1 = 0.f;
    float accO[8][4];
#pragma unroll
    for (int nt = 0; nt < 8; nt++)
#pragma unroll
        for (int i = 0; i < 4; i++) accO[nt][i] = 0.f;

    for (int ki = 0; ki < 8; ki++) {
        int st = ki & 1;
        if (ki > 0) {
            if (ki == 7) CP_WAIT0(); else CP_WAIT1();
            __syncthreads();
        }

        // ---- S = Q K^T
        float accS[16][4];
#pragma unroll
        for (int nt = 0; nt < 16; nt++)
#pragma unroll
            for (int i = 0; i < 4; i++) accS[nt][i] = 0.f;
#pragma unroll
        for (int ks = 0; ks < 4; ks++) {
#pragma unroll
            for (int p = 0; p < 8; p++) {
                uint32_t br = p * 16 + ((lane >> 4) << 3) + (lane & 7);
                uint32_t bc = ks * 16 + (((lane >> 3) & 1) << 3);
                uint32_t rh[4];
                ldsm4(rh, ub + uK + st * 18432 + br * 144 + bc * 2);
                uint32_t b0h[2] = {rh[0], rh[1]}, b1h[2] = {rh[2], rh[3]};
                mmaf16(accS[2*p],     qA[ks], b0h);
                mmaf16(accS[2*p + 1], qA[ks], b1h);
            }
        }

        bool band_tile = (ki >= qi - 1) && (ki <= qi + 1);
        float tmax0 = -1e30f, tmax1 = -1e30f;
        if (!band_tile) {
            float qa0 = (ki < qi) ? qw0_0 : qw32_0;
            float qa1 = (ki < qi) ? qw0_1 : qw32_1;
#pragma unroll
            for (int nt = 0; nt < 16; nt++) {
                accS[nt][0] = (accS[nt][0] + qa0) * 0.125f;
                accS[nt][1] = (accS[nt][1] + qa0) * 0.125f;
                accS[nt][2] = (accS[nt][2] + qa1) * 0.125f;
                accS[nt][3] = (accS[nt][3] + qa1) * 0.125f;
                tmax0 = fmaxf(tmax0, fmaxf(accS[nt][0], accS[nt][1]));
                tmax1 = fmaxf(tmax1, fmaxf(accS[nt][2], accS[nt][3]));
            }
        } else {
#pragma unroll
            for (int nt = 0; nt < 16; nt++) {
#pragma unroll
                for (int e = 0; e < 4; e++) {
                    int colg = ki * 128 + nt * 8 + ((lane & 3) << 1) + (e & 1);
                    int rg   = (e < 2) ? rowg0 : rowg1;
                    int lr   = (e < 2) ? lrow0 : lrow1;
                    int d = colg - rg;
                    float qr;
                    if (d < -16)      qr = (e < 2) ? qw0_0  : qw0_1;
                    else if (d > 16)  qr = (e < 2) ? qw32_0 : qw32_1;
                    else              qr = qrel_s[lr * 34 + d + 16];
                    float s = (accS[nt][e] + qr) * 0.125f;
                    if (d >= -16 && d <= 16) band_s[lr * 33 + d + 16] = s;
                    accS[nt][e] = s;
                    if (e < 2) tmax0 = fmaxf(tmax0, s); else tmax1 = fmaxf(tmax1, s);
                }
            }
        }
        tmax0 = fmaxf(tmax0, __shfl_xor_sync(0xffffffffu, tmax0, 1));
        tmax0 = fmaxf(tmax0, __shfl_xor_sync(0xffffffffu, tmax0, 2));
        tmax1 = fmaxf(tmax1, __shfl_xor_sync(0xffffffffu, tmax1, 1));
        tmax1 = fmaxf(tmax1, __shfl_xor_sync(0xffffffffu, tmax1, 2));

        float mn0 = fmaxf(m0, tmax0), mn1 = fmaxf(m1, tmax1);
        float sc0 = __expf(m0 - mn0), sc1 = __expf(m1 - mn1);
        m0 = mn0; m1 = mn1;
        l0 *= sc0; sL0 *= sc0; sR0 *= sc0;
        l1 *= sc1; sL1 *= sc1; sR1 *= sc1;
#pragma unroll
        for (int nt = 0; nt < 8; nt++) {
            accO[nt][0] *= sc0; accO[nt][1] *= sc0;
            accO[nt][2] *= sc1; accO[nt][3] *= sc1;
        }

        float es0 = 0.f, es1 = 0.f, eL0 = 0.f, eL1 = 0.f, eR0 = 0.f, eR1 = 0.f;
        if (!band_tile) {
#pragma unroll
            for (int nt = 0; nt < 16; nt++) {
                float e0 = __expf(accS[nt][0] - m0); accS[nt][0] = e0;
                float e1 = __expf(accS[nt][1] - m0); accS[nt][1] = e1;
                float e2 = __expf(accS[nt][2] - m1); accS[nt][2] = e2;
                float e3 = __expf(accS[nt][3] - m1); accS[nt][3] = e3;
                es0 += e0 + e1; es1 += e2 + e3;
            }
            if (ki < qi) { eL0 = es0; eL1 = es1; }
            else         { eR0 = es0; eR1 = es1; }
        } else {
#pragma unroll
            for (int nt = 0; nt < 16; nt++) {
#pragma unroll
                for (int e = 0; e < 4; e++) {
                    int colg = ki * 128 + nt * 8 + ((lane & 3) << 1) + (e & 1);
                    int rg = (e < 2) ? rowg0 : rowg1;
                    int d = colg - rg;
                    float mm = (e < 2) ? m0 : m1;
                    float ev = __expf(accS[nt][e] - mm);
                    accS[nt][e] = ev;
                    if (e < 2) {
                        es0 += ev;
                        if (d < -16) eL0 += ev; else if (d > 16) eR0 += ev;
                    } else {
                        es1 += ev;
                        if (d < -16) eL1 += ev; else if (d > 16) eR1 += ev;
                    }
                }
            }
        }
#pragma unroll
        for (int o = 1; o <= 2; o <<= 1) {
            es0 += __shfl_xor_sync(0xffffffffu, es0, o);
            es1 += __shfl_xor_sync(0xffffffffu, es1, o);
            eL0 += __shfl_xor_sync(0xffffffffu, eL0, o);
            eL1 += __shfl_xor_sync(0xffffffffu, eL1, o);
            eR0 += __shfl_xor_sync(0xffffffffu, eR0, o);
            eR1 += __shfl_xor_sync(0xffffffffu, eR1, o);
        }
        l0 += es0; sL0 += eL0; sR0 += eR0;
        l1 += es1; sL1 += eL1; sR1 += eR1;

        // ---- pack P as fp16 in A-fragment order
        uint32_t ph[16][2];
#pragma unroll
        for (int nt = 0; nt < 16; nt++) {
            ph[nt][0] = hpk2(__float2half_rn(accS[nt][0]), __float2half_rn(accS[nt][1]));
            ph[nt][1] = hpk2(__float2half_rn(accS[nt][2]), __float2half_rn(accS[nt][3]));
        }

        // ---- O += P V
#pragma unroll
        for (int ks2 = 0; ks2 < 8; ks2++) {
            uint32_t aH[4] = { ph[2*ks2][0], ph[2*ks2][1], ph[2*ks2+1][0], ph[2*ks2+1][1] };
#pragma unroll
            for (int p = 0; p < 4; p++) {
                uint32_t br = p * 16 + ((lane >> 4) << 3) + (lane & 7);
                uint32_t bc = ks2 * 16 + (((lane >> 3) & 1) << 3);
                uint32_t rh[4];
                ldsm4(rh, ub + uV + st * 17408 + br * 272 + bc * 2);
                uint32_t b0h[2] = {rh[0], rh[1]}, b1h[2] = {rh[2], rh[3]};
                mmaf16(accO[2*p],     aH, b0h);
                mmaf16(accO[2*p + 1], aH, b1h);
            }
        }

        __syncthreads();
        if (ki < 6) { FISSUE_KV(ki + 2, st); CP_COMMIT(); }
    }
#undef FISSUE_KV

    if ((lane & 3) == 0) {
        stat_s[lrow0 * 2] = m0; stat_s[lrow0 * 2 + 1] = l0;
        stat_s[lrow1 * 2] = m1; stat_s[lrow1 * 2 + 1] = l1;
    }
    __syncthreads();
    if (tid < 128) {
        float mm = stat_s[tid * 2], invl = 1.f / stat_s[tid * 2 + 1];
#pragma unroll
        for (int j = 0; j < 33; j++)
            band_s[tid * 33 + j] = __expf(band_s[tid * 33 + j] - mm) * invl;
    }
    __syncthreads();

    float inv0 = 1.f / l0, inv1 = 1.f / l1;
    float pa0 = sL0 * inv0, pb0 = sR0 * inv0;
    float pa1 = sL1 * inv1, pb1 = sR1 * inv1;
#pragma unroll
    for (int nt = 0; nt < 8; nt++) {
        int c0 = nt * 8 + ((lane & 3) << 1);
        accO[nt][0] = accO[nt][0] * inv0 + pa0 * relv_s[c0]     + pb0 * relv_s[32*64 + c0];
        accO[nt][1] = accO[nt][1] * inv0 + pa0 * relv_s[c0 + 1] + pb0 * relv_s[32*64 + c0 + 1];
        accO[nt][2] = accO[nt][2] * inv1 + pa1 * relv_s[c0]     + pb1 * relv_s[32*64 + c0];
        accO[nt][3] = accO[nt][3] * inv1 + pa1 * relv_s[c0 + 1] + pb1 * relv_s[32*64 + c0 + 1];
    }
#pragma unroll
    for (int j = 0; j < 33; j++) {
        float bp0 = band_s[lrow0 * 33 + j];
        float bp1 = band_s[lrow1 * 33 + j];
        const float* rv = relv_s + j * 64;
#pragma unroll
        for (int nt = 0; nt < 8; nt++) {
            int c0 = nt * 8 + ((lane & 3) << 1);
            float r0 = rv[c0], r1 = rv[c0 + 1];
            accO[nt][0] += bp0 * r0; accO[nt][1] += bp0 * r1;
            accO[nt][2] += bp1 * r0; accO[nt][3] += bp1 * r1;
        }
    }

    size_t obase = (size_t)(bB * 1024 + qi * 128) * 1024 + hh * 64;
#pragma unroll
    for (int nt = 0; nt < 8; nt++) {
        int c0 = nt * 8 + ((lane & 3) << 1);
        *(uint32_t*)(AT + obase + (size_t)lrow0 * 1024 + c0) =
            hpk2(__float2half_rn(accO[nt][0]), __float2half_rn(accO[nt][1]));
        *(uint32_t*)(AT + obase + (size_t)lrow1 * 1024 + c0) =
            hpk2(__float2half_rn(accO[nt][2]), __float2half_rn(accO[nt][3]));
    }
}

// ---------------- W [K,N] fp32 -> Wt [N,K] fp16 -------------------------------
__global__ void convert_wt_kernel(const float* __restrict__ W, fp16* __restrict__ o,
                                  int K, int N)
{
    __shared__ float t[32][33];
    int n0 = blockIdx.x * 32, k0 = blockIdx.y * 32;
    int tx = threadIdx.x, ty = threadIdx.y;
    for (int i = ty; i < 32; i += 8)
        t[i][tx] = W[(size_t)(k0 + i) * N + n0 + tx];
    __syncthreads();
    for (int i = ty; i < 32; i += 8)
        o[(size_t)(n0 + i) * K + k0 + tx] = __float2half_rn(t[tx][i]);
}

// ---------------- fused q/k/v fp32 -> fp16 ------------------------------------
__global__ void split3_kernel(const float* __restrict__ q, const float* __restrict__ k,
                              const float* __restrict__ v,
                              fp16* __restrict__ qo, fp16* __restrict__ ko, fp16* __restrict__ vo)
{
    const float* X = (blockIdx.y == 0) ? q : (blockIdx.y == 1) ? k : v;
    fp16* O = (blockIdx.y == 0) ? qo : (blockIdx.y == 1) ? ko : vo;
    size_t i = ((size_t)blockIdx.x * 256 + threadIdx.x) * 4;
    float4 w = *(const float4*)(X + i);
    *(uint2*)(O + i) = make_uint2(hpk2(__float2half_rn(w.x), __float2half_rn(w.y)),
                                  hpk2(__float2half_rn(w.z), __float2half_rn(w.w)));
}

// ---------------- V: [b,l,h*64+d] fp16 -> Vt [bh][d][l] fp16 ------------------
__global__ void transpose_v(const fp16* __restrict__ V, fp16* __restrict__ o)
{
    __shared__ fp16 t[32][34];
    int bh = blockIdx.z; int b = bh >> 4, h = bh & 15;
    int l0 = blockIdx.x * 32, d0 = blockIdx.y * 32;
    for (int i = threadIdx.y; i < 32; i += 8)
        t[i][threadIdx.x] = V[(size_t)(b * LL + l0 + i) * DD + h * DKK + d0 + threadIdx.x];
    __syncthreads();
    for (int i = threadIdx.y; i < 32; i += 8)
        o[((size_t)bh * DKK + d0 + i) * LL + l0 + threadIdx.x] = t[threadIdx.x][i];
}

// ---------------- qrel[b,l,h,r] = Qh[b,l,h,:] . rel_k[r,:] --------------------
__global__ void qrel_kernel(const fp16* __restrict__ Q, const float* __restrict__ rel_k,
                            float* __restrict__ qrel)
{
    __shared__ float rk[NREL * DKK];
    int t = threadIdx.x;
    for (int i = t; i < NREL * DKK; i += 256) rk[i] = rel_k[i];
    __syncthreads();
    int w = t >> 5, lane = t & 31;
    int item = blockIdx.x * 8 + w;
    int bl = item >> 4, h = item & 15;
    size_t i0 = (size_t)bl * DD + h * DKK + lane * 2;
    float q0 = __half2float(Q[i0]);
    float q1 = __half2float(Q[i0 + 1]);
    for (int r = 0; r < NREL; r++) {
        float v = q0 * rk[r * DKK + lane * 2] + q1 * rk[r * DKK + lane * 2 + 1];
        v += __shfl_xor_sync(0xffffffffu, v, 16);
        v += __shfl_xor_sync(0xffffffffu, v, 8);
        v += __shfl_xor_sync(0xffffffffu, v, 4);
        v += __shfl_xor_sync(0xffffffffu, v, 2);
        v += __shfl_xor_sync(0xffffffffu, v, 1);
        if (lane == 0) qrel[(size_t)item * NREL + r] = v;
    }
}

// ---------------- residual add + layernorm (vectorized) -----------------------
__global__ void ln_kernel(const float* __restrict__ X, const float* __restrict__ R,
                          const float* __restrict__ g, const float* __restrict__ be,
                          float* __restrict__ out, fp16* __restrict__ oh)
{
    int row = blockIdx.x, t = threadIdx.x;
    __shared__ float red[256];
    float4 v = *(const float4*)(X + (size_t)row * DD + t * 4);
    float4 r4 = *(const float4*)(R + (size_t)row * DD + t * 4);
    v.x += r4.x; v.y += r4.y; v.z += r4.z; v.w += r4.w;
    float s1 = v.x + v.y + v.z + v.w;
    red[t] = s1; __syncthreads();
    for (int s = 128; s > 0; s >>= 1) { if (t < s) red[t] += red[t + s]; __syncthreads(); }
    float mu = red[0] * (1.f / 1024.f);
    __syncthreads();
    float dx = v.x - mu, dy = v.y - mu, dz = v.z - mu, dw = v.w - mu;
    red[t] = dx * dx + dy * dy + dz * dz + dw * dw; __syncthreads();
    for (int s = 128; s > 0; s >>= 1) { if (t < s) red[t] += red[t + s]; __syncthreads(); }
    float rstd = rsqrtf(red[0] * (1.f / 1024.f) + 1e-6f);
    float4 g4 = *(const float4*)(g + t * 4);
    float4 b4 = *(const float4*)(be + t * 4);
    float4 o4;
    o4.x = dx * rstd * g4.x + b4.x;
    o4.y = dy * rstd * g4.y + b4.y;
    o4.z = dz * rstd * g4.z + b4.z;
    o4.w = dw * rstd * g4.w + b4.w;
    *(float4*)(out + (size_t)row * DD + t * 4) = o4;
    if (oh) {
        *(uint2*)(oh + (size_t)row * DD + t * 4) =
            make_uint2(hpk2(__float2half_rn(o4.x), __float2half_rn(o4.y)),
                       hpk2(__float2half_rn(o4.z), __float2half_rn(o4.w)));
    }
}

// ---------------- launch ------------------------------------------------------
extern "C" void kernel_launch(void* const* d_in, const int* in_sizes, int n_in,
                              void* d_out, int out_size)
{
    const float* q    = (const float*)d_in[0];
    const float* k    = (const float*)d_in[1];
    const float* v    = (const float*)d_in[2];
    const float* wq   = (const float*)d_in[3];
    const float* bq   = (const float*)d_in[4];
    const float* wk   = (const float*)d_in[5];
    const float* bk   = (const float*)d_in[6];
    const float* wv   = (const float*)d_in[7];
    const float* bv   = (const float*)d_in[8];
    const float* wfc  = (const float*)d_in[9];
    const float* bfc  = (const float*)d_in[10];
    const float* w1   = (const float*)d_in[11];
    const float* b1   = (const float*)d_in[12];
    const float* w2   = (const float*)d_in[13];
    const float* b2   = (const float*)d_in[14];
    const float* ln_g = (const float*)d_in[15];
    const float* ln_b = (const float*)d_in[16];
    const float* rel_k= (const float*)d_in[17];
    const float* rel_v= (const float*)d_in[18];
    float* out = (float*)d_out;

    float *gqrel, *gfc, *gx1, *gy;
    cudaGetSymbolAddress((void**)&gqrel, g_qrel);
    cudaGetSymbolAddress((void**)&gfc, g_fc);
    cudaGetSymbolAddress((void**)&gx1, g_x1);
    cudaGetSymbolAddress((void**)&gy, g_y);

    fp16 *wqt,*wkt,*wvt,*wft,*w1t,*w2t,*qs,*ks,*vs,*Qs,*Kb,*Vp,*Vt,*AT,*x1s,*hid;
    cudaGetSymbolAddress((void**)&wqt, g_wqt);
    cudaGetSymbolAddress((void**)&wkt, g_wkt);
    cudaGetSymbolAddress((void**)&wvt, g_wvt);
    cudaGetSymbolAddress((void**)&wft, g_wft);
    cudaGetSymbolAddress((void**)&w1t, g_w1t);
    cudaGetSymbolAddress((void**)&w2t, g_w2t);
    cudaGetSymbolAddress((void**)&qs, g_qs);
    cudaGetSymbolAddress((void**)&ks, g_ks);
    cudaGetSymbolAddress((void**)&vs, g_vs);
    cudaGetSymbolAddress((void**)&Qs, g_Qs);
    cudaGetSymbolAddress((void**)&Kb, g_Kb);
    cudaGetSymbolAddress((void**)&Vp, g_Vp);
    cudaGetSymbolAddress((void**)&Vt, g_Vt);
    cudaGetSymbolAddress((void**)&AT, g_AT);
    cudaGetSymbolAddress((void**)&x1s, g_x1s);
    cudaGetSymbolAddress((void**)&hid, g_hid);

    const int SMG = 3 * 36864;       // 110592 B per CTA (2 CTAs/SM)
    const int SMFLASH = 133888;
    cudaFuncSetAttribute(hgemm<0,0>, cudaFuncAttributeMaxDynamicSharedMemorySize, SMG);
    cudaFuncSetAttribute(hgemm<0,1>, cudaFuncAttributeMaxDynamicSharedMemorySize, SMG);
    cudaFuncSetAttribute(hgemm<1,1>, cudaFuncAttributeMaxDynamicSharedMemorySize, SMG);
    cudaFuncSetAttribute(flash_kernel, cudaFuncAttributeMaxDynamicSharedMemorySize, SMFLASH);

    // prep
    split3_kernel<<<dim3(MTOK*DD/1024, 3), 256>>>(q, k, v, qs, ks, vs);
    convert_wt_kernel<<<dim3(32,32),  dim3(32,8)>>>(wq,  wqt, DD, DD);
    convert_wt_kernel<<<dim3(32,32),  dim3(32,8)>>>(wk,  wkt, DD, DD);
    convert_wt_kernel<<<dim3(32,32),  dim3(32,8)>>>(wv,  wvt, DD, DD);

    // projections (hgemm in the ncu -s 5 window)
    hgemm<0,1><<<dim3(8,64),256,SMG>>>(qs, wqt, bq, nullptr, Qs, DD, DD, DD, DD);
    hgemm<0,1><<<dim3(8,64),256,SMG>>>(ks, wkt, bk, nullptr, Kb, DD, DD, DD, DD);
    hgemm<0,1><<<dim3(8,64),256,SMG>>>(vs, wvt, bv, nullptr, Vp, DD, DD, DD, DD);

    // remaining weight converts + V repack + qrel
    convert_wt_kernel<<<dim3(32,32),  dim3(32,8)>>>(wfc, wft, DD, DD);
    convert_wt_kernel<<<dim3(128,32), dim3(32,8)>>>(w1, w1t, DD, DI);
    convert_wt_kernel<<<dim3(32,128), dim3(32,8)>>>(w2, w2t, DI, DD);
    transpose_v<<<dim3(32,2,BB*HH), dim3(32,8)>>>(Vp, Vt);
    qrel_kernel<<<MTOK*HH/8, 256>>>(Qs, rel_k, gqrel);

    // fused attention -> AT (fp16)
    flash_kernel<<<dim3(8, BB*HH), 256, SMFLASH>>>(Qs, Kb, Vt, gqrel, rel_v, AT);

    // fc + residual(q) + LN
    hgemm<0,0><<<dim3(8,64),256,SMG>>>(AT, wft, bfc, gfc, nullptr, DD, DD, DD, DD);
    ln_kernel<<<MTOK,256>>>(gfc, q, ln_g, ln_b, gx1, x1s);

    // FFN + residual + LN -> out
    hgemm<1,1><<<dim3(32,64),256,SMG>>>(x1s, w1t, b1, nullptr, hid, DD, DD, DD, DI);
    hgemm<0,0><<<dim3(8,64),256,SMG>>>(hid, w2t, b2, gy, nullptr, DI, DI, DI, DD);
    ln_kernel<<<MTOK,256>>>(gy, gx1, ln_g, ln_b, out, nullptr);
}